// round 15
// baseline (speedup 1.0000x reference)
#include <cuda_runtime.h>

// FFT_19490561589800: batch of 16384 x 1024-point FFT of real input.
// Output: [real plane (16384x1024), imag plane (16384x1024)] fp32.
//
// Four-step FFT, 1024 = 32 x 32; one warp per TWO real rows packed as one
// complex FFT (Hermitian trick). Packed f32x2 butterflies; 0.5 folded into
// input. Epilogue: Z staged natural-order in shared, outputs written as
// 256-bit st.global.L2::evict_last.v8.b32 (output stays dirty-resident in L2
// across graph replays; sm_103a only allows the policy on 256-bit accesses).

static constexpr int N = 1024;

__device__ __host__ constexpr int br5(int i){
    return ((i & 1) << 4) | ((i & 2) << 2) | (i & 4) | ((i & 8) >> 2) | ((i & 16) >> 4);
}

// ---------- packed complex: (re = lo 32 bits, im = hi 32 bits) ----------
typedef unsigned long long cplx;

__device__ __host__ constexpr cplx packc(float lo, float hi){
    return (cplx)__builtin_bit_cast(unsigned int, lo)
         | ((cplx)__builtin_bit_cast(unsigned int, hi) << 32);
}

__device__ __forceinline__ cplx cpack(float x, float y){
    cplx r; asm("mov.b64 %0, {%1, %2};" : "=l"(r) : "f"(x), "f"(y)); return r;
}
__device__ __forceinline__ float2 cunpack(cplx a){
    float2 f; asm("mov.b64 {%0, %1}, %2;" : "=f"(f.x), "=f"(f.y) : "l"(a)); return f;
}
__device__ __forceinline__ cplx cadd(cplx a, cplx b){
    cplx r; asm("add.rn.f32x2 %0, %1, %2;" : "=l"(r) : "l"(a), "l"(b)); return r;
}
__device__ __forceinline__ cplx csub(cplx a, cplx b){
    cplx r; asm("sub.rn.f32x2 %0, %1, %2;" : "=l"(r) : "l"(a), "l"(b)); return r;
}
__device__ __forceinline__ cplx cmulel(cplx a, cplx b){   // elementwise
    cplx r; asm("mul.rn.f32x2 %0, %1, %2;" : "=l"(r) : "l"(a), "l"(b)); return r;
}
// r = d * (c + i*s), cc = (c,c), ss = (-s,s):  r = d*cc + swap(d)*ss
__device__ __forceinline__ cplx ctw(cplx d, cplx cc, cplx ss){
    float2 fd = cunpack(d);
    cplx dsw = cpack(fd.y, fd.x);
    cplx t, r;
    asm("mul.rn.f32x2 %0, %1, %2;" : "=l"(t) : "l"(dsw), "l"(ss));
    asm("fma.rn.f32x2 %0, %1, %2, %3;" : "=l"(r) : "l"(d), "l"(cc), "l"(t));
    return r;
}

__device__ __forceinline__ float2 cmulf(float2 a, float2 b){
    return make_float2(fmaf(a.x, b.x, -(a.y * b.y)),
                       fmaf(a.x, b.y,  (a.y * b.x)));
}

// 256-bit store with evict_last (required vector width for this policy)
__device__ __forceinline__ void stg8_el(float* p, const float* v){
    asm volatile("st.global.L2::evict_last.v8.b32 [%0], "
                 "{%1, %2, %3, %4, %5, %6, %7, %8};"
                 :: "l"(p), "f"(v[0]), "f"(v[1]), "f"(v[2]), "f"(v[3]),
                            "f"(v[4]), "f"(v[5]), "f"(v[6]), "f"(v[7])
                 : "memory");
}

// One DIF radix-2 stage of an in-register 32-point FFT (packed math).
template<int LEN>
__device__ __forceinline__ void fft32_stage(cplx* v){
    constexpr int HALF = LEN / 2;
    constexpr int TS   = 32 / LEN;
    constexpr float C[16] = {
        1.0f,                 0.98078528040323044f, 0.92387953251128674f, 0.83146961230254524f,
        0.70710678118654752f, 0.55557023301960222f, 0.38268343236508977f, 0.19509032201612825f,
        0.0f,                -0.19509032201612825f,-0.38268343236508977f,-0.55557023301960222f,
       -0.70710678118654752f,-0.83146961230254524f,-0.92387953251128674f,-0.98078528040323044f};
    constexpr float S[16] = {
        0.0f,                -0.19509032201612825f,-0.38268343236508977f,-0.55557023301960222f,
       -0.70710678118654752f,-0.83146961230254524f,-0.92387953251128674f,-0.98078528040323044f,
       -1.0f,                -0.98078528040323044f,-0.92387953251128674f,-0.83146961230254524f,
       -0.70710678118654752f,-0.55557023301960222f,-0.38268343236508977f,-0.19509032201612825f};
#pragma unroll
    for (int base = 0; base < 32; base += LEN){
#pragma unroll
        for (int j = 0; j < HALF; j++){
            cplx a = v[base + j];
            cplx b = v[base + j + HALF];
            cplx s = cadd(a, b);
            cplx d = csub(a, b);
            const int tj = j * TS;   // compile-time after unroll
            cplx r;
            if (tj == 0){
                r = d;
            } else if (tj == 8){                     // * (-i)
                float2 fd = cunpack(d);
                r = cpack(fd.y, -fd.x);
            } else {
                r = ctw(d, packc(C[tj], C[tj]), packc(-S[tj], S[tj]));
            }
            v[base + j]        = s;
            v[base + j + HALF] = r;
        }
    }
}

__device__ __forceinline__ void fft32(cplx* v){
    fft32_stage<32>(v);
    fft32_stage<16>(v);
    fft32_stage<8>(v);
    fft32_stage<4>(v);
    fft32_stage<2>(v);
}

#define PAIRS_PER_BLOCK 4
#define THREADS 128

__global__ void __launch_bounds__(THREADS, 4)
fft_kernel(const float* __restrict__ x,
           const float* __restrict__ twr,   // tw_real_3: cos(2*pi*j/1024), j<512
           const float* __restrict__ twi,   // tw_imag_3: -sin(2*pi*j/1024)
           float* __restrict__ out,
           int n_rows)
{
    // per-warp buffers: 33-pad for transpose, dense 1024 for epilogue staging
    __shared__ float s_re[PAIRS_PER_BLOCK][33 * 32];
    __shared__ float s_im[PAIRS_PER_BLOCK][33 * 32];

    const int t = threadIdx.x & 31;    // lane
    const int w = threadIdx.x >> 5;    // warp in block = pair in block
    const int pair = blockIdx.x * PAIRS_PER_BLOCK + w;
    const int rowa = pair * 2;
    const int rowb = rowa + 1;
    if (rowb >= n_rows) return;

    const float* xa = x + (size_t)rowa * N;
    const float* xb = x + (size_t)rowb * N;
    float* sre = s_re[w];
    float* sim = s_im[w];

    // ---- load: z[n] = 0.5*(xa[n] + i*xb[n]) ----
    cplx v[32];
#pragma unroll
    for (int n1 = 0; n1 < 32; n1++){
        v[n1] = cmulel(cpack(__ldg(xa + 32 * n1 + t), __ldg(xb + 32 * n1 + t)),
                       packc(0.5f, 0.5f));
    }

    // ---- stage A: 32-pt FFT over n1 ----
    fft32(v);                       // v[i] = A[br5(i)]

    // ---- inter-stage twiddle: A[k1] *= W_1024^{t*k1}, dual chains ----
    {
        const float2 b1 = make_float2(twr[t], twi[t]);   // W_1024^t
        const float2 b2 = cmulf(b1, b1);                 // W_1024^{2t}
        float2 cur_o = b1;   // k1 = 1, 3, 5, ...
        float2 cur_e = b2;   // k1 = 2, 4, 6, ...
#pragma unroll
        for (int k1 = 1; k1 < 32; k1 += 2){
            float2 f = cmulf(cunpack(v[br5(k1)]), cur_o);
            v[br5(k1)] = cpack(f.x, f.y);
            cur_o = cmulf(cur_o, b2);
        }
#pragma unroll
        for (int k1 = 2; k1 < 32; k1 += 2){
            float2 f = cmulf(cunpack(v[br5(k1)]), cur_e);
            v[br5(k1)] = cpack(f.x, f.y);
            cur_e = cmulf(cur_e, b2);
        }
    }

    // ---- transpose via shared: (k1, n2=t) -> thread t becomes k1 ----
#pragma unroll
    for (int i = 0; i < 32; i++){
        const int k1 = br5(i);
        const float2 f = cunpack(v[i]);
        sre[k1 * 33 + t] = f.x;
        sim[k1 * 33 + t] = f.y;
    }
    __syncwarp();
#pragma unroll
    for (int n2 = 0; n2 < 32; n2++){
        v[n2] = cpack(sre[t * 33 + n2], sim[t * 33 + n2]);
    }
    __syncwarp();   // WAR before dense reuse below

    // ---- stage B: 32-pt FFT over n2 ----
    fft32(v);                       // v[i] = Z[t + 32*br5(i)], prescaled by 0.5

    // ---- store Z to shared in natural order k = t + 32*k2 ----
#pragma unroll
    for (int i = 0; i < 32; i++){
        const int k2 = br5(i);
        const float2 f = cunpack(v[i]);
        sre[t + 32 * k2] = f.x;
        sim[t + 32 * k2] = f.y;
    }
    __syncwarp();

    // ---- Hermitian unpack, 8-wide: thread t owns k0 = 8t + 256j ----
    // mirror of [k0..k0+7] = element (1024-k0)&1023 (e=0) plus aligned chunk
    // c0 = (1016-k0)&1023 reversed (e=1..7 -> c0+7..c0+1).
    const size_t IMOFF = (size_t)n_rows * N;
    float* oar = out + (size_t)rowa * N;
    float* oai = oar + IMOFF;
    float* obr = oar + N;
    float* obi = obr + IMOFF;

#pragma unroll
    for (int j = 0; j < 4; j++){
        const int k0 = 8 * t + 256 * j;
        const int c0 = (1016 - k0) & (N - 1);
        const int c1 = (1024 - k0) & (N - 1);

        const float4 zr0 = *(const float4*)(sre + k0);
        const float4 zr1 = *(const float4*)(sre + k0 + 4);
        const float4 zi0 = *(const float4*)(sim + k0);
        const float4 zi1 = *(const float4*)(sim + k0 + 4);
        const float4 mr0 = *(const float4*)(sre + c0);
        const float4 mr1 = *(const float4*)(sre + c0 + 4);
        const float4 mi0 = *(const float4*)(sim + c0);
        const float4 mi1 = *(const float4*)(sim + c0 + 4);
        const float wre0 = sre[c1];
        const float wim0 = sim[c1];

        const float zr[8] = {zr0.x, zr0.y, zr0.z, zr0.w, zr1.x, zr1.y, zr1.z, zr1.w};
        const float zi[8] = {zi0.x, zi0.y, zi0.z, zi0.w, zi1.x, zi1.y, zi1.z, zi1.w};
        // wr[e] = Z[(1024-k0-e)&1023].re : e=0 -> c1[0]; e>=1 -> c0[8-e]
        const float wr[8] = {wre0, mr1.w, mr1.z, mr1.y, mr1.x, mr0.w, mr0.z, mr0.y};
        const float wi[8] = {wim0, mi1.w, mi1.z, mi1.y, mi1.x, mi0.w, mi0.z, mi0.y};

        float ar[8], ai[8], br[8], bi[8];
#pragma unroll
        for (int e = 0; e < 8; e++){
            ar[e] = zr[e] + wr[e];     // Re X_a  (0.5 folded in)
            ai[e] = zi[e] - wi[e];     // Im X_a
            br[e] = zi[e] + wi[e];     // Re X_b
            bi[e] = wr[e] - zr[e];     // Im X_b
        }
        stg8_el(oar + k0, ar);
        stg8_el(oai + k0, ai);
        stg8_el(obr + k0, br);
        stg8_el(obi + k0, bi);
    }
}

extern "C" void kernel_launch(void* const* d_in, const int* in_sizes, int n_in,
                              void* d_out, int out_size)
{
    const float* x   = (const float*)d_in[0];
    const float* twr = (const float*)d_in[10];   // tw_real_3 (512: W_1024^j)
    const float* twi = (const float*)d_in[11];   // tw_imag_3
    float* out = (float*)d_out;

    const int n_rows = in_sizes[0] / N;          // 16384
    const int pairs  = n_rows / 2;               // 8192
    const int blocks = (pairs + PAIRS_PER_BLOCK - 1) / PAIRS_PER_BLOCK;  // 2048

    fft_kernel<<<blocks, THREADS>>>(x, twr, twi, out, n_rows);
}

// round 16
// speedup vs baseline: 1.0454x; 1.0454x over previous
#include <cuda_runtime.h>

// FFT_19490561589800: batch of 16384 x 1024-point FFT of real input.
// Output: [real plane (16384x1024), imag plane (16384x1024)] fp32.
//
// Four-step FFT, 1024 = 32 x 32; one warp per TWO real rows packed as one
// complex FFT (Hermitian trick). Packed f32x2 butterflies; 64-bit shuffle
// Hermitian mirror (no epilogue shared round trip); 0.5 folded into input.
// Input loads use .cs (streaming, evict-on-use) to shrink the read stream's
// L2 footprint and leave more ways for dirty output lines. Stores are plain
// (L2-policy experiments on the store side regressed twice).

static constexpr int N = 1024;

__device__ __host__ constexpr int br5(int i){
    return ((i & 1) << 4) | ((i & 2) << 2) | (i & 4) | ((i & 8) >> 2) | ((i & 16) >> 4);
}

// ---------- packed complex: (re = lo 32 bits, im = hi 32 bits) ----------
typedef unsigned long long cplx;

__device__ __host__ constexpr cplx packc(float lo, float hi){
    return (cplx)__builtin_bit_cast(unsigned int, lo)
         | ((cplx)__builtin_bit_cast(unsigned int, hi) << 32);
}

__device__ __forceinline__ cplx cpack(float x, float y){
    cplx r; asm("mov.b64 %0, {%1, %2};" : "=l"(r) : "f"(x), "f"(y)); return r;
}
__device__ __forceinline__ float2 cunpack(cplx a){
    float2 f; asm("mov.b64 {%0, %1}, %2;" : "=f"(f.x), "=f"(f.y) : "l"(a)); return f;
}
__device__ __forceinline__ cplx cadd(cplx a, cplx b){
    cplx r; asm("add.rn.f32x2 %0, %1, %2;" : "=l"(r) : "l"(a), "l"(b)); return r;
}
__device__ __forceinline__ cplx csub(cplx a, cplx b){
    cplx r; asm("sub.rn.f32x2 %0, %1, %2;" : "=l"(r) : "l"(a), "l"(b)); return r;
}
__device__ __forceinline__ cplx cmulel(cplx a, cplx b){   // elementwise
    cplx r; asm("mul.rn.f32x2 %0, %1, %2;" : "=l"(r) : "l"(a), "l"(b)); return r;
}
// r = d * (c + i*s), cc = (c,c), ss = (-s,s):  r = d*cc + swap(d)*ss
__device__ __forceinline__ cplx ctw(cplx d, cplx cc, cplx ss){
    float2 fd = cunpack(d);
    cplx dsw = cpack(fd.y, fd.x);
    cplx t, r;
    asm("mul.rn.f32x2 %0, %1, %2;" : "=l"(t) : "l"(dsw), "l"(ss));
    asm("fma.rn.f32x2 %0, %1, %2, %3;" : "=l"(r) : "l"(d), "l"(cc), "l"(t));
    return r;
}

__device__ __forceinline__ float2 cmulf(float2 a, float2 b){
    return make_float2(fmaf(a.x, b.x, -(a.y * b.y)),
                       fmaf(a.x, b.y,  (a.y * b.x)));
}

// One DIF radix-2 stage of an in-register 32-point FFT (packed math).
template<int LEN>
__device__ __forceinline__ void fft32_stage(cplx* v){
    constexpr int HALF = LEN / 2;
    constexpr int TS   = 32 / LEN;
    constexpr float C[16] = {
        1.0f,                 0.98078528040323044f, 0.92387953251128674f, 0.83146961230254524f,
        0.70710678118654752f, 0.55557023301960222f, 0.38268343236508977f, 0.19509032201612825f,
        0.0f,                -0.19509032201612825f,-0.38268343236508977f,-0.55557023301960222f,
       -0.70710678118654752f,-0.83146961230254524f,-0.92387953251128674f,-0.98078528040323044f};
    constexpr float S[16] = {
        0.0f,                -0.19509032201612825f,-0.38268343236508977f,-0.55557023301960222f,
       -0.70710678118654752f,-0.83146961230254524f,-0.92387953251128674f,-0.98078528040323044f,
       -1.0f,                -0.98078528040323044f,-0.92387953251128674f,-0.83146961230254524f,
       -0.70710678118654752f,-0.55557023301960222f,-0.38268343236508977f,-0.19509032201612825f};
#pragma unroll
    for (int base = 0; base < 32; base += LEN){
#pragma unroll
        for (int j = 0; j < HALF; j++){
            cplx a = v[base + j];
            cplx b = v[base + j + HALF];
            cplx s = cadd(a, b);
            cplx d = csub(a, b);
            const int tj = j * TS;   // compile-time after unroll
            cplx r;
            if (tj == 0){
                r = d;
            } else if (tj == 8){                     // * (-i)
                float2 fd = cunpack(d);
                r = cpack(fd.y, -fd.x);
            } else {
                r = ctw(d, packc(C[tj], C[tj]), packc(-S[tj], S[tj]));
            }
            v[base + j]        = s;
            v[base + j + HALF] = r;
        }
    }
}

__device__ __forceinline__ void fft32(cplx* v){
    fft32_stage<32>(v);
    fft32_stage<16>(v);
    fft32_stage<8>(v);
    fft32_stage<4>(v);
    fft32_stage<2>(v);
}

#define PAIRS_PER_BLOCK 4
#define THREADS 128

__global__ void __launch_bounds__(THREADS, 4)
fft_kernel(const float* __restrict__ x,
           const float* __restrict__ twr,   // tw_real_3: cos(2*pi*j/1024), j<512
           const float* __restrict__ twi,   // tw_imag_3: -sin(2*pi*j/1024)
           float* __restrict__ out,
           int n_rows)
{
    // per-warp transpose buffers: 32x32 with pad 33 (conflict-free both phases)
    __shared__ float s_re[PAIRS_PER_BLOCK][33 * 32];
    __shared__ float s_im[PAIRS_PER_BLOCK][33 * 32];

    const int t = threadIdx.x & 31;    // lane
    const int w = threadIdx.x >> 5;    // warp in block = pair in block
    const int pair = blockIdx.x * PAIRS_PER_BLOCK + w;
    const int rowa = pair * 2;
    const int rowb = rowa + 1;
    if (rowb >= n_rows) return;

    const float* xa = x + (size_t)rowa * N;
    const float* xb = x + (size_t)rowb * N;
    float* sre = s_re[w];
    float* sim = s_im[w];

    // ---- load (streaming .cs): z[n] = 0.5*(xa[n] + i*xb[n]) ----
    cplx v[32];
#pragma unroll
    for (int n1 = 0; n1 < 32; n1++){
        v[n1] = cmulel(cpack(__ldcs(xa + 32 * n1 + t), __ldcs(xb + 32 * n1 + t)),
                       packc(0.5f, 0.5f));
    }

    // ---- stage A: 32-pt FFT over n1 ----
    fft32(v);                       // v[i] = A[br5(i)]

    // ---- inter-stage twiddle: A[k1] *= W_1024^{t*k1}, dual chains ----
    {
        const float2 b1 = make_float2(twr[t], twi[t]);   // W_1024^t
        const float2 b2 = cmulf(b1, b1);                 // W_1024^{2t}
        float2 cur_o = b1;   // k1 = 1, 3, 5, ...
        float2 cur_e = b2;   // k1 = 2, 4, 6, ...
#pragma unroll
        for (int k1 = 1; k1 < 32; k1 += 2){
            float2 f = cmulf(cunpack(v[br5(k1)]), cur_o);
            v[br5(k1)] = cpack(f.x, f.y);
            cur_o = cmulf(cur_o, b2);
        }
#pragma unroll
        for (int k1 = 2; k1 < 32; k1 += 2){
            float2 f = cmulf(cunpack(v[br5(k1)]), cur_e);
            v[br5(k1)] = cpack(f.x, f.y);
            cur_e = cmulf(cur_e, b2);
        }
    }

    // ---- transpose via shared: (k1, n2=t) -> thread t becomes k1 ----
#pragma unroll
    for (int i = 0; i < 32; i++){
        const int k1 = br5(i);
        const float2 f = cunpack(v[i]);
        sre[k1 * 33 + t] = f.x;
        sim[k1 * 33 + t] = f.y;
    }
    __syncwarp();
#pragma unroll
    for (int n2 = 0; n2 < 32; n2++){
        v[n2] = cpack(sre[t * 33 + n2], sim[t * 33 + n2]);
    }
    // no further shared-memory use

    // ---- stage B: 32-pt FFT over n2 ----
    fft32(v);                       // v[i] = Z[t + 32*br5(i)], prescaled by 0.5

    // ---- Hermitian unpack fully in registers via 64-bit warp shuffle ----
    // For k = t + 32*k2 (k2 = br5(i)), mirror Z[(1024-k)&1023]:
    //   t != 0 : lane 32-t, register br5(31-k2)
    //   t == 0 : lane 0,    register br5((32-k2)&31)
    const size_t IMOFF = (size_t)n_rows * N;
    float* oar = out + (size_t)rowa * N;
    float* oai = oar + IMOFF;
    float* obr = oar + N;
    float* obi = obr + IMOFF;

    const int srcLane = (32 - t) & 31;
#pragma unroll
    for (int i = 0; i < 32; i++){
        const int k2 = br5(i);
        const int i2 = br5(31 - k2);          // mirror register for t != 0
        const int i0 = br5((32 - k2) & 31);   // mirror register for t == 0

        cplx wsh = __shfl_sync(0xffffffffu, v[i2], srcLane);
        if (t == 0) wsh = v[i0];

        const float2 z  = cunpack(v[i]);
        const float2 wv = cunpack(wsh);
        const int k = t + 32 * k2;
        oar[k] = z.x + wv.x;     // Re X_a
        oai[k] = z.y - wv.y;     // Im X_a
        obr[k] = z.y + wv.y;     // Re X_b
        obi[k] = wv.x - z.x;     // Im X_b
    }
}

extern "C" void kernel_launch(void* const* d_in, const int* in_sizes, int n_in,
                              void* d_out, int out_size)
{
    const float* x   = (const float*)d_in[0];
    const float* twr = (const float*)d_in[10];   // tw_real_3 (512: W_1024^j)
    const float* twi = (const float*)d_in[11];   // tw_imag_3
    float* out = (float*)d_out;

    const int n_rows = in_sizes[0] / N;          // 16384
    const int pairs  = n_rows / 2;               // 8192
    const int blocks = (pairs + PAIRS_PER_BLOCK - 1) / PAIRS_PER_BLOCK;  // 2048

    fft_kernel<<<blocks, THREADS>>>(x, twr, twi, out, n_rows);
}